// round 8
// baseline (speedup 1.0000x reference)
#include <cuda_runtime.h>
#include <cuda_bf16.h>
#include <cstdint>
#include <cstddef>

#define N_NODES  100000
#define N_EDGES  300000
#define N_GRAPHS 2048
#define F_ATOM   40
#define D_IN     128
#define D_HID    256
#define D_OUT    512

// ---------------- scratch (device globals; no runtime alloc allowed) ----------------
__device__ float g_bufA[(size_t)N_NODES * D_OUT];   // ping
__device__ float g_bufB[(size_t)N_NODES * D_OUT];   // pong
__device__ float g_bufZ[(size_t)N_NODES * D_HID];   // (1+eps)*h + agg   (max D needed = 256)
__device__ float g_pooled[(size_t)N_GRAPHS * D_OUT];
__device__ int   g_is64;                            // 1 if index arrays are int64, 0 if int32

// ---------------- index dtype detection ----------------
// Read the first n_elems 32-bit words of the buffer (safe under BOTH interpretations:
// int32 data has exactly n_elems words; int64 data has 2*n_elems). If the data is
// int64 with values < 2^31, every odd word (little-endian high word) is 0. If the
// data is int32, odd words are actual random indices -> OR is nonzero.
__global__ void detect_kernel(const unsigned int* __restrict__ w, int n_words) {
    __shared__ unsigned int sh[32];
    unsigned int acc = 0;
    int nhalf = n_words >> 1;
    for (int i = threadIdx.x; i < nhalf; i += blockDim.x)
        acc |= w[2 * i + 1];
    #pragma unroll
    for (int o = 16; o > 0; o >>= 1) acc |= __shfl_down_sync(0xFFFFFFFFu, acc, o);
    if ((threadIdx.x & 31) == 0) sh[threadIdx.x >> 5] = acc;
    __syncthreads();
    if (threadIdx.x == 0) {
        unsigned int t = 0;
        for (int i = 0; i < (int)(blockDim.x >> 5); i++) t |= sh[i];
        g_is64 = (t == 0u) ? 1 : 0;
    }
}

__device__ __forceinline__ long long load_idx(const void* __restrict__ p, int i) {
    if (g_is64) return ((const long long*)p)[i];
    return (long long)(((const int*)p)[i]);
}

// ---------------- embed: out[N,128] = x[N,40] @ W[40,128] + b ----------------
__global__ void embed_kernel(const float* __restrict__ x, const float* __restrict__ W,
                             const float* __restrict__ b, float* __restrict__ out) {
    __shared__ float xs[4][F_ATOM];
    int r0 = blockIdx.x * 4;
    int t  = threadIdx.x;             // 128 threads, one output col each
    for (int i = t; i < 4 * F_ATOM; i += 128) {
        int r = i / F_ATOM, c = i % F_ATOM;
        if (r0 + r < N_NODES) xs[r][c] = x[(size_t)(r0 + r) * F_ATOM + c];
    }
    __syncthreads();
    float bj = b[t];
    #pragma unroll
    for (int r = 0; r < 4; r++) {
        if (r0 + r >= N_NODES) return;
        float acc = bj;
        #pragma unroll
        for (int k = 0; k < F_ATOM; k++)
            acc = fmaf(xs[r][k], W[k * D_IN + t], acc);
        out[(size_t)(r0 + r) * D_IN + t] = acc;
    }
}

// ---------------- z = (1+eps[l]) * h  (full overwrite; no memset needed) ----------------
__global__ void scale_copy_kernel(float* __restrict__ z, const float* __restrict__ h,
                                  const float* __restrict__ eps, int l, size_t n4) {
    float s = 1.0f + eps[l];
    size_t i = (size_t)blockIdx.x * blockDim.x + threadIdx.x;
    size_t stride = (size_t)gridDim.x * blockDim.x;
    const float4* h4 = (const float4*)h;
    float4* z4 = (float4*)z;
    for (; i < n4; i += stride) {
        float4 v = h4[i];
        v.x *= s; v.y *= s; v.z *= s; v.w *= s;
        z4[i] = v;
    }
}

// ---------------- edge scatter: z[dst] += h[src] (one warp per edge) ----------------
__global__ void edge_agg_kernel(float* __restrict__ z, const float* __restrict__ h,
                                const void* __restrict__ ei, int D) {
    int warp = (int)((blockIdx.x * (size_t)blockDim.x + threadIdx.x) >> 5);
    int lane = threadIdx.x & 31;
    if (warp >= N_EDGES) return;
    long long s = load_idx(ei, warp);            // src (row 0)
    long long d = load_idx(ei, N_EDGES + warp);  // dst (row 1)
    const float* hs = h + (size_t)s * D;
    float*       zd = z + (size_t)d * D;
    for (int c = lane; c < D; c += 32)
        atomicAdd(&zd[c], hs[c]);
}

// ---------------- fused SGEMM: C = act(A[M,K] @ B[K,N] + bias) ----------------
// 128x128 tile, BK=8, 256 threads, 8x8 micro-tile per thread.
#define BM 128
#define BN 128
#define BK 8
__global__ __launch_bounds__(256, 2)
void gemm_bias_act(const float* __restrict__ A, const float* __restrict__ B,
                   const float* __restrict__ bias, float* __restrict__ C,
                   int M, int N, int K, int do_relu) {
    __shared__ float As[BK][BM];
    __shared__ float Bs[BK][BN];

    int tid = threadIdx.x;
    int tx  = tid & 15;          // 0..15 -> col group
    int ty  = tid >> 4;          // 0..15 -> row group
    int block_row = blockIdx.y * BM;
    int block_col = blockIdx.x * BN;

    // A loader: one float4 per thread. tile = 128 rows x 8 cols
    int a_row = tid >> 1;            // 0..127
    int a_col = (tid & 1) * 4;       // 0 or 4
    // B loader: one float4 per thread. tile = 8 rows x 128 cols
    int b_row = tid >> 5;            // 0..7
    int b_col = (tid & 31) * 4;      // 0..124

    float acc[8][8];
    #pragma unroll
    for (int i = 0; i < 8; i++)
        #pragma unroll
        for (int j = 0; j < 8; j++) acc[i][j] = 0.0f;

    for (int k0 = 0; k0 < K; k0 += BK) {
        int gr = block_row + a_row;
        float4 av = make_float4(0.f, 0.f, 0.f, 0.f);
        if (gr < M) av = *(const float4*)(A + (size_t)gr * K + k0 + a_col);
        As[a_col + 0][a_row] = av.x;
        As[a_col + 1][a_row] = av.y;
        As[a_col + 2][a_row] = av.z;
        As[a_col + 3][a_row] = av.w;

        float4 bv = *(const float4*)(B + (size_t)(k0 + b_row) * N + block_col + b_col);
        *(float4*)&Bs[b_row][b_col] = bv;
        __syncthreads();

        #pragma unroll
        for (int k = 0; k < BK; k++) {
            float ra[8], rb[8];
            *(float4*)&ra[0] = *(const float4*)&As[k][ty * 8];
            *(float4*)&ra[4] = *(const float4*)&As[k][ty * 8 + 4];
            *(float4*)&rb[0] = *(const float4*)&Bs[k][tx * 8];
            *(float4*)&rb[4] = *(const float4*)&Bs[k][tx * 8 + 4];
            #pragma unroll
            for (int i = 0; i < 8; i++)
                #pragma unroll
                for (int j = 0; j < 8; j++)
                    acc[i][j] = fmaf(ra[i], rb[j], acc[i][j]);
        }
        __syncthreads();
    }

    // epilogue: bias + optional relu
    #pragma unroll
    for (int i = 0; i < 8; i++) {
        int gr = block_row + ty * 8 + i;
        if (gr >= M) continue;
        #pragma unroll
        for (int j4 = 0; j4 < 8; j4 += 4) {
            int gc = block_col + tx * 8 + j4;
            float4 bv = *(const float4*)(bias + gc);
            float4 v;
            v.x = acc[i][j4 + 0] + bv.x;
            v.y = acc[i][j4 + 1] + bv.y;
            v.z = acc[i][j4 + 2] + bv.z;
            v.w = acc[i][j4 + 3] + bv.w;
            if (do_relu) {
                v.x = fmaxf(v.x, 0.f); v.y = fmaxf(v.y, 0.f);
                v.z = fmaxf(v.z, 0.f); v.w = fmaxf(v.w, 0.f);
            }
            *(float4*)(C + (size_t)gr * N + gc) = v;
        }
    }
}

// ---------------- zero pooled ----------------
__global__ void zero_kernel(float* __restrict__ p, size_t n) {
    size_t i = (size_t)blockIdx.x * blockDim.x + threadIdx.x;
    size_t stride = (size_t)gridDim.x * blockDim.x;
    for (; i < n; i += stride) p[i] = 0.0f;
}

// ---------------- pool: pooled[batch[n]] += h[n]; batch is SORTED -> run-compress ----------------
// block = 128 threads, each owns 4 of the 512 dims, processes 64 consecutive nodes.
__global__ void pool_kernel(const float* __restrict__ h, const void* __restrict__ batch,
                            float* __restrict__ pooled) {
    int n0 = blockIdx.x * 64;
    if (n0 >= N_NODES) return;
    int t = threadIdx.x;
    int nEnd = min(n0 + 64, N_NODES);
    float acc[4] = {0.f, 0.f, 0.f, 0.f};
    long long curg = load_idx(batch, n0);
    for (int n = n0; n < nEnd; n++) {
        long long g = load_idx(batch, n);
        if (g != curg) {
            #pragma unroll
            for (int i = 0; i < 4; i++) {
                atomicAdd(&pooled[(size_t)curg * D_OUT + t + 128 * i], acc[i]);
                acc[i] = 0.f;
            }
            curg = g;
        }
        #pragma unroll
        for (int i = 0; i < 4; i++)
            acc[i] += h[(size_t)n * D_OUT + t + 128 * i];
    }
    #pragma unroll
    for (int i = 0; i < 4; i++)
        atomicAdd(&pooled[(size_t)curg * D_OUT + t + 128 * i], acc[i]);
}

// ---------------- head: out[g] = pooled[g,:] . W_task + b_task ----------------
__global__ void task_kernel(const float* __restrict__ pooled, const float* __restrict__ Wt,
                            const float* __restrict__ bt, float* __restrict__ out) {
    int g = blockIdx.x;
    int t = threadIdx.x;      // 128 threads
    float s = 0.f;
    #pragma unroll
    for (int i = 0; i < 4; i++)
        s += pooled[(size_t)g * D_OUT + t + 128 * i] * Wt[t + 128 * i];
    // warp reduce
    #pragma unroll
    for (int o = 16; o > 0; o >>= 1) s += __shfl_down_sync(0xFFFFFFFFu, s, o);
    __shared__ float red[4];
    if ((t & 31) == 0) red[t >> 5] = s;
    __syncthreads();
    if (t == 0) out[g] = red[0] + red[1] + red[2] + red[3] + bt[0];
}

// ---------------- launch ----------------
extern "C" void kernel_launch(void* const* d_in, const int* in_sizes, int n_in,
                              void* d_out, int out_size) {
    const float* x       = (const float*)d_in[0];
    const void*  ei      = d_in[1];                 // int32 OR int64, detected at runtime
    const void*  batch   = d_in[2];                 // same dtype as ei
    const float* W_embed = (const float*)d_in[3];
    const float* b_embed = (const float*)d_in[4];
    const float* eps     = (const float*)d_in[5];
    const float* W1[3]   = {(const float*)d_in[6],  (const float*)d_in[10], (const float*)d_in[14]};
    const float* b1[3]   = {(const float*)d_in[7],  (const float*)d_in[11], (const float*)d_in[15]};
    const float* W2[3]   = {(const float*)d_in[8],  (const float*)d_in[12], (const float*)d_in[16]};
    const float* b2[3]   = {(const float*)d_in[9],  (const float*)d_in[13], (const float*)d_in[17]};
    const float* W_task  = (const float*)d_in[18];
    const float* b_task  = (const float*)d_in[19];
    float* out = (float*)d_out;

    float *bufA, *bufB, *bufZ, *pooled;
    cudaGetSymbolAddress((void**)&bufA, g_bufA);
    cudaGetSymbolAddress((void**)&bufB, g_bufB);
    cudaGetSymbolAddress((void**)&bufZ, g_bufZ);
    cudaGetSymbolAddress((void**)&pooled, g_pooled);

    const int Din[3] = {D_IN,  D_HID, D_HID};   // input dim to each layer
    const int Dh[3]  = {D_HID, D_HID, D_OUT};   // hidden/out dim of each layer's MLP

    // 0) detect index dtype (int32 vs int64) from the edge_index buffer.
    //    in_sizes[1] = element count (2 * N_EDGES); reading that many 32-bit words
    //    is in-bounds under both interpretations.
    detect_kernel<<<1, 1024>>>((const unsigned int*)ei, in_sizes[1]);

    // 1) embed -> bufA [N, 128]
    embed_kernel<<<N_NODES / 4, 128>>>(x, W_embed, b_embed, bufA);

    float* hcur = bufA;
    float* hnext = bufB;
    for (int l = 0; l < 3; l++) {
        int dk = Din[l], dh = Dh[l];
        // z = (1+eps)*h  (full overwrite)
        size_t n4 = (size_t)N_NODES * dk / 4;
        scale_copy_kernel<<<2048, 256>>>(bufZ, hcur, eps, l, n4);
        // z[dst] += h[src]
        edge_agg_kernel<<<(N_EDGES * 32 + 255) / 256, 256>>>(bufZ, hcur, ei, dk);
        // t = relu(z @ W1 + b1)  -> hnext used as temp [N, dh]
        {
            dim3 grid(dh / BN, (N_NODES + BM - 1) / BM);
            gemm_bias_act<<<grid, 256>>>(bufZ, W1[l], b1[l], hnext, N_NODES, dh, dk, 1);
        }
        // h = (t @ W2 + b2), relu if l < 2  -> write into hcur (ping-pong scratch)
        {
            dim3 grid(dh / BN, (N_NODES + BM - 1) / BM);
            gemm_bias_act<<<grid, 256>>>(hnext, W2[l], b2[l], hcur, N_NODES, dh, dh, (l < 2) ? 1 : 0);
        }
    }

    // pool over sorted batch
    zero_kernel<<<256, 256>>>(pooled, (size_t)N_GRAPHS * D_OUT);
    pool_kernel<<<(N_NODES + 63) / 64, 128>>>(hcur, batch, pooled);

    // head
    task_kernel<<<N_GRAPHS, 128>>>(pooled, W_task, b_task, out);
}

// round 13
// speedup vs baseline: 2.0455x; 2.0455x over previous
#include <cuda_runtime.h>
#include <cuda_bf16.h>
#include <cstdint>
#include <cstddef>

#define N_NODES  100000
#define N_EDGES  300000
#define N_GRAPHS 2048
#define F_ATOM   40
#define D_IN     128
#define D_HID    256
#define D_OUT    512

// ---------------- scratch (device globals; no runtime alloc allowed) ----------------
__device__ float g_bufA[(size_t)N_NODES * D_OUT];   // ping
__device__ float g_bufB[(size_t)N_NODES * D_OUT];   // pong
__device__ float g_bufZ[(size_t)N_NODES * D_HID];   // (1+eps)*h + agg   (max D needed = 256)
__device__ float g_pooled[(size_t)N_GRAPHS * D_OUT];
__device__ int   g_is64;                            // 1 if index arrays are int64, 0 if int32

// ---------------- index dtype detection ----------------
__global__ void detect_kernel(const unsigned int* __restrict__ w, int n_words) {
    __shared__ unsigned int sh[32];
    unsigned int acc = 0;
    int nhalf = n_words >> 1;
    for (int i = threadIdx.x; i < nhalf; i += blockDim.x)
        acc |= w[2 * i + 1];
    #pragma unroll
    for (int o = 16; o > 0; o >>= 1) acc |= __shfl_down_sync(0xFFFFFFFFu, acc, o);
    if ((threadIdx.x & 31) == 0) sh[threadIdx.x >> 5] = acc;
    __syncthreads();
    if (threadIdx.x == 0) {
        unsigned int t = 0;
        for (int i = 0; i < (int)(blockDim.x >> 5); i++) t |= sh[i];
        g_is64 = (t == 0u) ? 1 : 0;
    }
}

__device__ __forceinline__ long long load_idx(const void* __restrict__ p, int i) {
    if (g_is64) return ((const long long*)p)[i];
    return (long long)(((const int*)p)[i]);
}

// ---------------- embed: out[N,128] = x[N,40] @ W[40,128] + b (fp32) ----------------
__global__ void embed_kernel(const float* __restrict__ x, const float* __restrict__ W,
                             const float* __restrict__ b, float* __restrict__ out) {
    __shared__ float xs[4][F_ATOM];
    int r0 = blockIdx.x * 4;
    int t  = threadIdx.x;
    for (int i = t; i < 4 * F_ATOM; i += 128) {
        int r = i / F_ATOM, c = i % F_ATOM;
        if (r0 + r < N_NODES) xs[r][c] = x[(size_t)(r0 + r) * F_ATOM + c];
    }
    __syncthreads();
    float bj = b[t];
    #pragma unroll
    for (int r = 0; r < 4; r++) {
        if (r0 + r >= N_NODES) return;
        float acc = bj;
        #pragma unroll
        for (int k = 0; k < F_ATOM; k++)
            acc = fmaf(xs[r][k], W[k * D_IN + t], acc);
        out[(size_t)(r0 + r) * D_IN + t] = acc;
    }
}

// ---------------- z = (1+eps[l]) * h ----------------
__global__ void scale_copy_kernel(float* __restrict__ z, const float* __restrict__ h,
                                  const float* __restrict__ eps, int l, size_t n4) {
    float s = 1.0f + eps[l];
    size_t i = (size_t)blockIdx.x * blockDim.x + threadIdx.x;
    size_t stride = (size_t)gridDim.x * blockDim.x;
    const float4* h4 = (const float4*)h;
    float4* z4 = (float4*)z;
    for (; i < n4; i += stride) {
        float4 v = h4[i];
        v.x *= s; v.y *= s; v.z *= s; v.w *= s;
        z4[i] = v;
    }
}

// ---------------- edge scatter: z[dst] += h[src] (one warp per edge) ----------------
__global__ void edge_agg_kernel(float* __restrict__ z, const float* __restrict__ h,
                                const void* __restrict__ ei, int D) {
    int warp = (int)((blockIdx.x * (size_t)blockDim.x + threadIdx.x) >> 5);
    int lane = threadIdx.x & 31;
    if (warp >= N_EDGES) return;
    long long s = load_idx(ei, warp);
    long long d = load_idx(ei, N_EDGES + warp);
    const float* hs = h + (size_t)s * D;
    float*       zd = z + (size_t)d * D;
    for (int c = lane; c < D; c += 32)
        atomicAdd(&zd[c], hs[c]);
}

// ---------------- tf32 tensor-core GEMM: C = act(A[M,K] @ B[K,N] + bias) ----------------
// BM=128 BN=128 BK=16, 256 threads = 8 warps, warp tile 64x32 (warp grid 2x4).
// Fragments per warp: 4 (m) x 4 (n) mma m16n8k8 tiles per k-step of 8.
#define BM 128
#define BN 128
#define BK 16
#define SPAD 136   // smem row stride (u32): 8*(lane%4)+lane/4 banks -> conflict-free frag loads

__device__ __forceinline__ unsigned int f2tf32(float f) {
    unsigned int u;
    asm("cvt.rna.tf32.f32 %0, %1;" : "=r"(u) : "f"(f));
    return u;
}

__global__ __launch_bounds__(256, 2)
void gemm_tf32(const float* __restrict__ A, const float* __restrict__ B,
               const float* __restrict__ bias, float* __restrict__ C,
               int M, int N, int K, int do_relu) {
    __shared__ unsigned int As[BK][SPAD];   // [k][m], tf32 bits
    __shared__ unsigned int Bs[BK][SPAD];   // [k][n], tf32 bits

    int tid  = threadIdx.x;
    int lane = tid & 31;
    int warp = tid >> 5;
    int wr = warp & 1;            // 0..1 : 64-row slab
    int wc = warp >> 1;           // 0..3 : 32-col slab
    int block_row = blockIdx.y * BM;
    int block_col = blockIdx.x * BN;

    // A loader: thread -> row r=tid>>1 (0..127), k-offset (tid&1)*8, 8 floats
    int a_r  = tid >> 1;
    int a_k  = (tid & 1) * 8;
    // B loader: thread -> k-row kr=tid>>4 (0..15), col (tid&15)*8, 8 floats
    int b_kr = tid >> 4;
    int b_c  = (tid & 15) * 8;

    float c[4][4][4];
    #pragma unroll
    for (int i = 0; i < 4; i++)
        #pragma unroll
        for (int j = 0; j < 4; j++) {
            c[i][j][0] = c[i][j][1] = c[i][j][2] = c[i][j][3] = 0.f;
        }

    int grow = block_row + a_r;
    const int lq = lane & 3;      // k within 4
    const int lg = lane >> 2;     // group id 0..7
    int mbase = wr * 64;
    int nbase = wc * 32;

    for (int k0 = 0; k0 < K; k0 += BK) {
        // load A 128x16 (transposed store, tf32-rounded)
        float4 av0 = make_float4(0.f,0.f,0.f,0.f), av1 = av0;
        if (grow < M) {
            const float* ap = A + (size_t)grow * K + k0 + a_k;
            av0 = *(const float4*)ap;
            av1 = *(const float4*)(ap + 4);
        }
        As[a_k + 0][a_r] = f2tf32(av0.x);
        As[a_k + 1][a_r] = f2tf32(av0.y);
        As[a_k + 2][a_r] = f2tf32(av0.z);
        As[a_k + 3][a_r] = f2tf32(av0.w);
        As[a_k + 4][a_r] = f2tf32(av1.x);
        As[a_k + 5][a_r] = f2tf32(av1.y);
        As[a_k + 6][a_r] = f2tf32(av1.z);
        As[a_k + 7][a_r] = f2tf32(av1.w);

        // load B 16x128
        {
            const float* bp = B + (size_t)(k0 + b_kr) * N + block_col + b_c;
            float4 bv0 = *(const float4*)bp;
            float4 bv1 = *(const float4*)(bp + 4);
            Bs[b_kr][b_c + 0] = f2tf32(bv0.x);
            Bs[b_kr][b_c + 1] = f2tf32(bv0.y);
            Bs[b_kr][b_c + 2] = f2tf32(bv0.z);
            Bs[b_kr][b_c + 3] = f2tf32(bv0.w);
            Bs[b_kr][b_c + 4] = f2tf32(bv1.x);
            Bs[b_kr][b_c + 5] = f2tf32(bv1.y);
            Bs[b_kr][b_c + 6] = f2tf32(bv1.z);
            Bs[b_kr][b_c + 7] = f2tf32(bv1.w);
        }
        __syncthreads();

        #pragma unroll
        for (int kk = 0; kk < 2; kk++) {
            int kq = kk * 8 + lq;
            unsigned int af[4][4], bf[4][2];
            #pragma unroll
            for (int mi = 0; mi < 4; mi++) {
                int mb = mbase + mi * 16 + lg;
                af[mi][0] = As[kq    ][mb];
                af[mi][1] = As[kq    ][mb + 8];
                af[mi][2] = As[kq + 4][mb];
                af[mi][3] = As[kq + 4][mb + 8];
            }
            #pragma unroll
            for (int ni = 0; ni < 4; ni++) {
                int nb = nbase + ni * 8 + lg;
                bf[ni][0] = Bs[kq    ][nb];
                bf[ni][1] = Bs[kq + 4][nb];
            }
            #pragma unroll
            for (int mi = 0; mi < 4; mi++)
                #pragma unroll
                for (int ni = 0; ni < 4; ni++) {
                    asm volatile(
                        "mma.sync.aligned.m16n8k8.row.col.f32.tf32.tf32.f32 "
                        "{%0,%1,%2,%3}, {%4,%5,%6,%7}, {%8,%9}, {%0,%1,%2,%3};"
                        : "+f"(c[mi][ni][0]), "+f"(c[mi][ni][1]),
                          "+f"(c[mi][ni][2]), "+f"(c[mi][ni][3])
                        : "r"(af[mi][0]), "r"(af[mi][1]), "r"(af[mi][2]), "r"(af[mi][3]),
                          "r"(bf[ni][0]), "r"(bf[ni][1]));
                }
        }
        __syncthreads();
    }

    // epilogue: bias + optional relu, guarded float2 stores
    #pragma unroll
    for (int mi = 0; mi < 4; mi++) {
        int r0 = block_row + mbase + mi * 16 + lg;
        int r1 = r0 + 8;
        #pragma unroll
        for (int ni = 0; ni < 4; ni++) {
            int gc = block_col + nbase + ni * 8 + lq * 2;
            float2 bv = *(const float2*)(bias + gc);
            float2 v0, v1;
            v0.x = c[mi][ni][0] + bv.x;  v0.y = c[mi][ni][1] + bv.y;
            v1.x = c[mi][ni][2] + bv.x;  v1.y = c[mi][ni][3] + bv.y;
            if (do_relu) {
                v0.x = fmaxf(v0.x, 0.f); v0.y = fmaxf(v0.y, 0.f);
                v1.x = fmaxf(v1.x, 0.f); v1.y = fmaxf(v1.y, 0.f);
            }
            if (r0 < M) *(float2*)(C + (size_t)r0 * N + gc) = v0;
            if (r1 < M) *(float2*)(C + (size_t)r1 * N + gc) = v1;
        }
    }
}

// ---------------- zero pooled ----------------
__global__ void zero_kernel(float* __restrict__ p, size_t n) {
    size_t i = (size_t)blockIdx.x * blockDim.x + threadIdx.x;
    size_t stride = (size_t)gridDim.x * blockDim.x;
    for (; i < n; i += stride) p[i] = 0.0f;
}

// ---------------- pool: pooled[batch[n]] += h[n]; batch SORTED -> run-compress ----------------
__global__ void pool_kernel(const float* __restrict__ h, const void* __restrict__ batch,
                            float* __restrict__ pooled) {
    int n0 = blockIdx.x * 64;
    if (n0 >= N_NODES) return;
    int t = threadIdx.x;
    int nEnd = min(n0 + 64, N_NODES);
    float acc[4] = {0.f, 0.f, 0.f, 0.f};
    long long curg = load_idx(batch, n0);
    for (int n = n0; n < nEnd; n++) {
        long long g = load_idx(batch, n);
        if (g != curg) {
            #pragma unroll
            for (int i = 0; i < 4; i++) {
                atomicAdd(&pooled[(size_t)curg * D_OUT + t + 128 * i], acc[i]);
                acc[i] = 0.f;
            }
            curg = g;
        }
        #pragma unroll
        for (int i = 0; i < 4; i++)
            acc[i] += h[(size_t)n * D_OUT + t + 128 * i];
    }
    #pragma unroll
    for (int i = 0; i < 4; i++)
        atomicAdd(&pooled[(size_t)curg * D_OUT + t + 128 * i], acc[i]);
}

// ---------------- head ----------------
__global__ void task_kernel(const float* __restrict__ pooled, const float* __restrict__ Wt,
                            const float* __restrict__ bt, float* __restrict__ out) {
    int g = blockIdx.x;
    int t = threadIdx.x;
    float s = 0.f;
    #pragma unroll
    for (int i = 0; i < 4; i++)
        s += pooled[(size_t)g * D_OUT + t + 128 * i] * Wt[t + 128 * i];
    #pragma unroll
    for (int o = 16; o > 0; o >>= 1) s += __shfl_down_sync(0xFFFFFFFFu, s, o);
    __shared__ float red[4];
    if ((t & 31) == 0) red[t >> 5] = s;
    __syncthreads();
    if (t == 0) out[g] = red[0] + red[1] + red[2] + red[3] + bt[0];
}

// ---------------- launch ----------------
extern "C" void kernel_launch(void* const* d_in, const int* in_sizes, int n_in,
                              void* d_out, int out_size) {
    const float* x       = (const float*)d_in[0];
    const void*  ei      = d_in[1];
    const void*  batch   = d_in[2];
    const float* W_embed = (const float*)d_in[3];
    const float* b_embed = (const float*)d_in[4];
    const float* eps     = (const float*)d_in[5];
    const float* W1[3]   = {(const float*)d_in[6],  (const float*)d_in[10], (const float*)d_in[14]};
    const float* b1[3]   = {(const float*)d_in[7],  (const float*)d_in[11], (const float*)d_in[15]};
    const float* W2[3]   = {(const float*)d_in[8],  (const float*)d_in[12], (const float*)d_in[16]};
    const float* b2[3]   = {(const float*)d_in[9],  (const float*)d_in[13], (const float*)d_in[17]};
    const float* W_task  = (const float*)d_in[18];
    const float* b_task  = (const float*)d_in[19];
    float* out = (float*)d_out;

    float *bufA, *bufB, *bufZ, *pooled;
    cudaGetSymbolAddress((void**)&bufA, g_bufA);
    cudaGetSymbolAddress((void**)&bufB, g_bufB);
    cudaGetSymbolAddress((void**)&bufZ, g_bufZ);
    cudaGetSymbolAddress((void**)&pooled, g_pooled);

    const int Din[3] = {D_IN,  D_HID, D_HID};
    const int Dh[3]  = {D_HID, D_HID, D_OUT};

    detect_kernel<<<1, 1024>>>((const unsigned int*)ei, in_sizes[1]);

    embed_kernel<<<N_NODES / 4, 128>>>(x, W_embed, b_embed, bufA);

    float* hcur = bufA;
    float* hnext = bufB;
    for (int l = 0; l < 3; l++) {
        int dk = Din[l], dh = Dh[l];
        size_t n4 = (size_t)N_NODES * dk / 4;
        scale_copy_kernel<<<2048, 256>>>(bufZ, hcur, eps, l, n4);
        edge_agg_kernel<<<(N_EDGES * 32 + 255) / 256, 256>>>(bufZ, hcur, ei, dk);
        {
            dim3 grid(dh / BN, (N_NODES + BM - 1) / BM);
            gemm_tf32<<<grid, 256>>>(bufZ, W1[l], b1[l], hnext, N_NODES, dh, dk, 1);
        }
        {
            dim3 grid(dh / BN, (N_NODES + BM - 1) / BM);
            gemm_tf32<<<grid, 256>>>(hnext, W2[l], b2[l], hcur, N_NODES, dh, dh, (l < 2) ? 1 : 0);
        }
    }

    zero_kernel<<<256, 256>>>(pooled, (size_t)N_GRAPHS * D_OUT);
    pool_kernel<<<(N_NODES + 63) / 64, 128>>>(hcur, batch, pooled);

    task_kernel<<<N_GRAPHS, 128>>>(pooled, W_task, b_task, out);
}

// round 14
// speedup vs baseline: 2.1634x; 1.0576x over previous
#include <cuda_runtime.h>
#include <cuda_bf16.h>
#include <cstdint>
#include <cstddef>

#define N_NODES  100000
#define N_EDGES  300000
#define N_GRAPHS 2048
#define F_ATOM   40
#define D_IN     128
#define D_HID    256
#define D_OUT    512

// ---------------- scratch (device globals; no runtime alloc allowed) ----------------
__device__ float g_bufA[(size_t)N_NODES * D_OUT];   // ping
__device__ float g_bufB[(size_t)N_NODES * D_OUT];   // pong
__device__ float g_bufZ[(size_t)N_NODES * D_HID];   // (1+eps)*h + agg   (max D needed = 256)
__device__ float g_pooled[(size_t)N_GRAPHS * D_OUT];
__device__ int   g_is64;                            // 1 if index arrays are int64, 0 if int32

// ---------------- index dtype detection ----------------
__global__ void detect_kernel(const unsigned int* __restrict__ w, int n_words) {
    __shared__ unsigned int sh[32];
    unsigned int acc = 0;
    int nhalf = n_words >> 1;
    for (int i = threadIdx.x; i < nhalf; i += blockDim.x)
        acc |= w[2 * i + 1];
    #pragma unroll
    for (int o = 16; o > 0; o >>= 1) acc |= __shfl_down_sync(0xFFFFFFFFu, acc, o);
    if ((threadIdx.x & 31) == 0) sh[threadIdx.x >> 5] = acc;
    __syncthreads();
    if (threadIdx.x == 0) {
        unsigned int t = 0;
        for (int i = 0; i < (int)(blockDim.x >> 5); i++) t |= sh[i];
        g_is64 = (t == 0u) ? 1 : 0;
    }
}

__device__ __forceinline__ long long load_idx(const void* __restrict__ p, int i) {
    if (g_is64) return ((const long long*)p)[i];
    return (long long)(((const int*)p)[i]);
}

// ---------------- embed: out[N,128] = x[N,40] @ W[40,128] + b (fp32) ----------------
__global__ void embed_kernel(const float* __restrict__ x, const float* __restrict__ W,
                             const float* __restrict__ b, float* __restrict__ out) {
    __shared__ float xs[4][F_ATOM];
    int r0 = blockIdx.x * 4;
    int t  = threadIdx.x;
    for (int i = t; i < 4 * F_ATOM; i += 128) {
        int r = i / F_ATOM, c = i % F_ATOM;
        if (r0 + r < N_NODES) xs[r][c] = x[(size_t)(r0 + r) * F_ATOM + c];
    }
    __syncthreads();
    float bj = b[t];
    #pragma unroll
    for (int r = 0; r < 4; r++) {
        if (r0 + r >= N_NODES) return;
        float acc = bj;
        #pragma unroll
        for (int k = 0; k < F_ATOM; k++)
            acc = fmaf(xs[r][k], W[k * D_IN + t], acc);
        out[(size_t)(r0 + r) * D_IN + t] = acc;
    }
}

// ---------------- z = (1+eps[l]) * h ----------------
__global__ void scale_copy_kernel(float* __restrict__ z, const float* __restrict__ h,
                                  const float* __restrict__ eps, int l, size_t n4) {
    float s = 1.0f + eps[l];
    size_t i = (size_t)blockIdx.x * blockDim.x + threadIdx.x;
    size_t stride = (size_t)gridDim.x * blockDim.x;
    const float4* h4 = (const float4*)h;
    float4* z4 = (float4*)z;
    for (; i < n4; i += stride) {
        float4 v = h4[i];
        v.x *= s; v.y *= s; v.z *= s; v.w *= s;
        z4[i] = v;
    }
}

// ---------------- edge scatter: z[dst] += h[src] (one warp per edge, red.v4) ----------------
__global__ void edge_agg_kernel(float* __restrict__ z, const float* __restrict__ h,
                                const void* __restrict__ ei, int D) {
    int warp = (int)((blockIdx.x * (size_t)blockDim.x + threadIdx.x) >> 5);
    int lane = threadIdx.x & 31;
    if (warp >= N_EDGES) return;
    long long s = load_idx(ei, warp);
    long long d = load_idx(ei, N_EDGES + warp);
    const float* hs = h + (size_t)s * D;
    float*       zd = z + (size_t)d * D;
    for (int c = lane * 4; c < D; c += 128) {
        float4 v = *(const float4*)(hs + c);
        asm volatile("red.global.add.v4.f32 [%0], {%1,%2,%3,%4};"
                     :: "l"(zd + c), "f"(v.x), "f"(v.y), "f"(v.z), "f"(v.w)
                     : "memory");
    }
}

// ---------------- tf32 tensor-core GEMM (2-stage pipelined): C = act(A@B + bias) ----------------
// BM=128 BN=128 BK=16, 256 threads = 8 warps, warp tile 64x32 (warp grid 2x4).
#define BM 128
#define BN 128
#define BK 16
#define SPAD 136

__device__ __forceinline__ unsigned int f2tf32(float f) {
    unsigned int u;
    asm("cvt.rna.tf32.f32 %0, %1;" : "=r"(u) : "f"(f));
    return u;
}

__global__ __launch_bounds__(256, 2)
void gemm_tf32(const float* __restrict__ A, const float* __restrict__ B,
               const float* __restrict__ bias, float* __restrict__ C,
               int M, int N, int K, int do_relu) {
    __shared__ unsigned int As[2][BK][SPAD];   // [buf][k][m], tf32 bits
    __shared__ unsigned int Bs[2][BK][SPAD];   // [buf][k][n], tf32 bits

    int tid  = threadIdx.x;
    int lane = tid & 31;
    int warp = tid >> 5;
    int wr = warp & 1;            // 0..1 : 64-row slab
    int wc = warp >> 1;           // 0..3 : 32-col slab
    int block_row = blockIdx.y * BM;
    int block_col = blockIdx.x * BN;

    int a_r  = tid >> 1;              // A loader: row 0..127
    int a_k  = (tid & 1) * 8;         // k-offset 0 or 8
    int b_kr = tid >> 4;              // B loader: k-row 0..15
    int b_c  = (tid & 15) * 8;        // col 0..120

    float c[4][4][4];
    #pragma unroll
    for (int i = 0; i < 4; i++)
        #pragma unroll
        for (int j = 0; j < 4; j++)
            c[i][j][0] = c[i][j][1] = c[i][j][2] = c[i][j][3] = 0.f;

    int grow = block_row + a_r;
    const int lq = lane & 3;
    const int lg = lane >> 2;
    int mbase = wr * 64;
    int nbase = wc * 32;

    float4 av0, av1, bv0, bv1;

    // ---- prologue: load tile 0 ----
    {
        av0 = make_float4(0.f,0.f,0.f,0.f); av1 = av0;
        if (grow < M) {
            const float* ap = A + (size_t)grow * K + a_k;
            av0 = *(const float4*)ap;
            av1 = *(const float4*)(ap + 4);
        }
        const float* bp = B + (size_t)b_kr * N + block_col + b_c;
        bv0 = *(const float4*)bp;
        bv1 = *(const float4*)(bp + 4);

        As[0][a_k + 0][a_r] = f2tf32(av0.x);
        As[0][a_k + 1][a_r] = f2tf32(av0.y);
        As[0][a_k + 2][a_r] = f2tf32(av0.z);
        As[0][a_k + 3][a_r] = f2tf32(av0.w);
        As[0][a_k + 4][a_r] = f2tf32(av1.x);
        As[0][a_k + 5][a_r] = f2tf32(av1.y);
        As[0][a_k + 6][a_r] = f2tf32(av1.z);
        As[0][a_k + 7][a_r] = f2tf32(av1.w);
        Bs[0][b_kr][b_c + 0] = f2tf32(bv0.x);
        Bs[0][b_kr][b_c + 1] = f2tf32(bv0.y);
        Bs[0][b_kr][b_c + 2] = f2tf32(bv0.z);
        Bs[0][b_kr][b_c + 3] = f2tf32(bv0.w);
        Bs[0][b_kr][b_c + 4] = f2tf32(bv1.x);
        Bs[0][b_kr][b_c + 5] = f2tf32(bv1.y);
        Bs[0][b_kr][b_c + 6] = f2tf32(bv1.z);
        Bs[0][b_kr][b_c + 7] = f2tf32(bv1.w);
    }
    __syncthreads();

    int buf = 0;
    for (int k0 = 0; k0 < K; k0 += BK) {
        bool has_next = (k0 + BK) < K;
        // ---- issue global loads for next tile (latency hidden behind compute) ----
        if (has_next) {
            int kn = k0 + BK;
            av0 = make_float4(0.f,0.f,0.f,0.f); av1 = av0;
            if (grow < M) {
                const float* ap = A + (size_t)grow * K + kn + a_k;
                av0 = *(const float4*)ap;
                av1 = *(const float4*)(ap + 4);
            }
            const float* bp = B + (size_t)(kn + b_kr) * N + block_col + b_c;
            bv0 = *(const float4*)bp;
            bv1 = *(const float4*)(bp + 4);
        }

        // ---- compute current tile ----
        #pragma unroll
        for (int kk = 0; kk < 2; kk++) {
            int kq = kk * 8 + lq;
            unsigned int af[4][4], bf[4][2];
            #pragma unroll
            for (int mi = 0; mi < 4; mi++) {
                int mb = mbase + mi * 16 + lg;
                af[mi][0] = As[buf][kq    ][mb];
                af[mi][1] = As[buf][kq    ][mb + 8];
                af[mi][2] = As[buf][kq + 4][mb];
                af[mi][3] = As[buf][kq + 4][mb + 8];
            }
            #pragma unroll
            for (int ni = 0; ni < 4; ni++) {
                int nb = nbase + ni * 8 + lg;
                bf[ni][0] = Bs[buf][kq    ][nb];
                bf[ni][1] = Bs[buf][kq + 4][nb];
            }
            #pragma unroll
            for (int mi = 0; mi < 4; mi++)
                #pragma unroll
                for (int ni = 0; ni < 4; ni++) {
                    asm volatile(
                        "mma.sync.aligned.m16n8k8.row.col.f32.tf32.tf32.f32 "
                        "{%0,%1,%2,%3}, {%4,%5,%6,%7}, {%8,%9}, {%0,%1,%2,%3};"
                        : "+f"(c[mi][ni][0]), "+f"(c[mi][ni][1]),
                          "+f"(c[mi][ni][2]), "+f"(c[mi][ni][3])
                        : "r"(af[mi][0]), "r"(af[mi][1]), "r"(af[mi][2]), "r"(af[mi][3]),
                          "r"(bf[ni][0]), "r"(bf[ni][1]));
                }
        }

        // ---- store next tile into the other buffer (overlaps with compute above) ----
        if (has_next) {
            int nb = buf ^ 1;
            As[nb][a_k + 0][a_r] = f2tf32(av0.x);
            As[nb][a_k + 1][a_r] = f2tf32(av0.y);
            As[nb][a_k + 2][a_r] = f2tf32(av0.z);
            As[nb][a_k + 3][a_r] = f2tf32(av0.w);
            As[nb][a_k + 4][a_r] = f2tf32(av1.x);
            As[nb][a_k + 5][a_r] = f2tf32(av1.y);
            As[nb][a_k + 6][a_r] = f2tf32(av1.z);
            As[nb][a_k + 7][a_r] = f2tf32(av1.w);
            Bs[nb][b_kr][b_c + 0] = f2tf32(bv0.x);
            Bs[nb][b_kr][b_c + 1] = f2tf32(bv0.y);
            Bs[nb][b_kr][b_c + 2] = f2tf32(bv0.z);
            Bs[nb][b_kr][b_c + 3] = f2tf32(bv0.w);
            Bs[nb][b_kr][b_c + 4] = f2tf32(bv1.x);
            Bs[nb][b_kr][b_c + 5] = f2tf32(bv1.y);
            Bs[nb][b_kr][b_c + 6] = f2tf32(bv1.z);
            Bs[nb][b_kr][b_c + 7] = f2tf32(bv1.w);
        }
        __syncthreads();
        buf ^= 1;
    }

    // epilogue: bias + optional relu, guarded float2 stores
    #pragma unroll
    for (int mi = 0; mi < 4; mi++) {
        int r0 = block_row + mbase + mi * 16 + lg;
        int r1 = r0 + 8;
        #pragma unroll
        for (int ni = 0; ni < 4; ni++) {
            int gc = block_col + nbase + ni * 8 + lq * 2;
            float2 bv = *(const float2*)(bias + gc);
            float2 v0, v1;
            v0.x = c[mi][ni][0] + bv.x;  v0.y = c[mi][ni][1] + bv.y;
            v1.x = c[mi][ni][2] + bv.x;  v1.y = c[mi][ni][3] + bv.y;
            if (do_relu) {
                v0.x = fmaxf(v0.x, 0.f); v0.y = fmaxf(v0.y, 0.f);
                v1.x = fmaxf(v1.x, 0.f); v1.y = fmaxf(v1.y, 0.f);
            }
            if (r0 < M) *(float2*)(C + (size_t)r0 * N + gc) = v0;
            if (r1 < M) *(float2*)(C + (size_t)r1 * N + gc) = v1;
        }
    }
}

// ---------------- zero pooled ----------------
__global__ void zero_kernel(float* __restrict__ p, size_t n) {
    size_t i = (size_t)blockIdx.x * blockDim.x + threadIdx.x;
    size_t stride = (size_t)gridDim.x * blockDim.x;
    for (; i < n; i += stride) p[i] = 0.0f;
}

// ---------------- pool: pooled[batch[n]] += h[n]; batch SORTED -> run-compress ----------------
__global__ void pool_kernel(const float* __restrict__ h, const void* __restrict__ batch,
                            float* __restrict__ pooled) {
    int n0 = blockIdx.x * 64;
    if (n0 >= N_NODES) return;
    int t = threadIdx.x;
    int nEnd = min(n0 + 64, N_NODES);
    float acc[4] = {0.f, 0.f, 0.f, 0.f};
    long long curg = load_idx(batch, n0);
    for (int n = n0; n < nEnd; n++) {
        long long g = load_idx(batch, n);
        if (g != curg) {
            #pragma unroll
            for (int i = 0; i < 4; i++) {
                atomicAdd(&pooled[(size_t)curg * D_OUT + t + 128 * i], acc[i]);
                acc[i] = 0.f;
            }
            curg = g;
        }
        #pragma unroll
        for (int i = 0; i < 4; i++)
            acc[i] += h[(size_t)n * D_OUT + t + 128 * i];
    }
    #pragma unroll
    for (int i = 0; i < 4; i++)
        atomicAdd(&pooled[(size_t)curg * D_OUT + t + 128 * i], acc[i]);
}

// ---------------- head ----------------
__global__ void task_kernel(const float* __restrict__ pooled, const float* __restrict__ Wt,
                            const float* __restrict__ bt, float* __restrict__ out) {
    int g = blockIdx.x;
    int t = threadIdx.x;
    float s = 0.f;
    #pragma unroll
    for (int i = 0; i < 4; i++)
        s += pooled[(size_t)g * D_OUT + t + 128 * i] * Wt[t + 128 * i];
    #pragma unroll
    for (int o = 16; o > 0; o >>= 1) s += __shfl_down_sync(0xFFFFFFFFu, s, o);
    __shared__ float red[4];
    if ((t & 31) == 0) red[t >> 5] = s;
    __syncthreads();
    if (t == 0) out[g] = red[0] + red[1] + red[2] + red[3] + bt[0];
}

// ---------------- launch ----------------
extern "C" void kernel_launch(void* const* d_in, const int* in_sizes, int n_in,
                              void* d_out, int out_size) {
    const float* x       = (const float*)d_in[0];
    const void*  ei      = d_in[1];
    const void*  batch   = d_in[2];
    const float* W_embed = (const float*)d_in[3];
    const float* b_embed = (const float*)d_in[4];
    const float* eps     = (const float*)d_in[5];
    const float* W1[3]   = {(const float*)d_in[6],  (const float*)d_in[10], (const float*)d_in[14]};
    const float* b1[3]   = {(const float*)d_in[7],  (const float*)d_in[11], (const float*)d_in[15]};
    const float* W2[3]   = {(const float*)d_in[8],  (const float*)d_in[12], (const float*)d_in[16]};
    const float* b2[3]   = {(const float*)d_in[9],  (const float*)d_in[13], (const float*)d_in[17]};
    const float* W_task  = (const float*)d_in[18];
    const float* b_task  = (const float*)d_in[19];
    float* out = (float*)d_out;

    float *bufA, *bufB, *bufZ, *pooled;
    cudaGetSymbolAddress((void**)&bufA, g_bufA);
    cudaGetSymbolAddress((void**)&bufB, g_bufB);
    cudaGetSymbolAddress((void**)&bufZ, g_bufZ);
    cudaGetSymbolAddress((void**)&pooled, g_pooled);

    const int Din[3] = {D_IN,  D_HID, D_HID};
    const int Dh[3]  = {D_HID, D_HID, D_OUT};

    detect_kernel<<<1, 1024>>>((const unsigned int*)ei, in_sizes[1]);

    embed_kernel<<<N_NODES / 4, 128>>>(x, W_embed, b_embed, bufA);

    float* hcur = bufA;
    float* hnext = bufB;
    for (int l = 0; l < 3; l++) {
        int dk = Din[l], dh = Dh[l];
        size_t n4 = (size_t)N_NODES * dk / 4;
        scale_copy_kernel<<<2048, 256>>>(bufZ, hcur, eps, l, n4);
        edge_agg_kernel<<<(N_EDGES * 32 + 255) / 256, 256>>>(bufZ, hcur, ei, dk);
        {
            dim3 grid(dh / BN, (N_NODES + BM - 1) / BM);
            gemm_tf32<<<grid, 256>>>(bufZ, W1[l], b1[l], hnext, N_NODES, dh, dk, 1);
        }
        {
            dim3 grid(dh / BN, (N_NODES + BM - 1) / BM);
            gemm_tf32<<<grid, 256>>>(hnext, W2[l], b2[l], hcur, N_NODES, dh, dh, (l < 2) ? 1 : 0);
        }
    }

    zero_kernel<<<256, 256>>>(pooled, (size_t)N_GRAPHS * D_OUT);
    pool_kernel<<<(N_NODES + 63) / 64, 128>>>(hcur, batch, pooled);

    task_kernel<<<N_GRAPHS, 128>>>(pooled, W_task, b_task, out);
}

// round 15
// speedup vs baseline: 2.3653x; 1.0933x over previous
#include <cuda_runtime.h>
#include <cuda_bf16.h>
#include <cstdint>
#include <cstddef>

#define N_NODES  100000
#define N_EDGES  300000
#define N_GRAPHS 2048
#define F_ATOM   40
#define D_IN     128
#define D_HID    256
#define D_OUT    512

// ---------------- scratch ----------------
__device__ float g_bufA[(size_t)N_NODES * D_OUT];   // ping
__device__ float g_bufB[(size_t)N_NODES * D_OUT];   // pong
__device__ float g_bufZ[(size_t)N_NODES * D_HID];   // (1+eps)*h + agg
__device__ float g_pooled[(size_t)N_GRAPHS * D_OUT];
__device__ int   g_is64;

// ---------------- index dtype detection ----------------
__global__ void detect_kernel(const unsigned int* __restrict__ w, int n_words) {
    __shared__ unsigned int sh[32];
    unsigned int acc = 0;
    int nhalf = n_words >> 1;
    for (int i = threadIdx.x; i < nhalf; i += blockDim.x)
        acc |= w[2 * i + 1];
    #pragma unroll
    for (int o = 16; o > 0; o >>= 1) acc |= __shfl_down_sync(0xFFFFFFFFu, acc, o);
    if ((threadIdx.x & 31) == 0) sh[threadIdx.x >> 5] = acc;
    __syncthreads();
    if (threadIdx.x == 0) {
        unsigned int t = 0;
        for (int i = 0; i < (int)(blockDim.x >> 5); i++) t |= sh[i];
        g_is64 = (t == 0u) ? 1 : 0;
    }
}

__device__ __forceinline__ long long load_idx(const void* __restrict__ p, int i) {
    if (g_is64) return ((const long long*)p)[i];
    return (long long)(((const int*)p)[i]);
}

// ---------------- embed (+ fused z0 = (1+eps[0])*h) ----------------
__global__ void embed_kernel(const float* __restrict__ x, const float* __restrict__ W,
                             const float* __restrict__ b, float* __restrict__ out,
                             float* __restrict__ Z, const float* __restrict__ epsv) {
    __shared__ float xs[4][F_ATOM];
    int r0 = blockIdx.x * 4;
    int t  = threadIdx.x;
    for (int i = t; i < 4 * F_ATOM; i += 128) {
        int r = i / F_ATOM, c = i % F_ATOM;
        if (r0 + r < N_NODES) xs[r][c] = x[(size_t)(r0 + r) * F_ATOM + c];
    }
    __syncthreads();
    float bj = b[t];
    float ze = 1.0f + epsv[0];
    #pragma unroll
    for (int r = 0; r < 4; r++) {
        if (r0 + r >= N_NODES) return;
        float acc = bj;
        #pragma unroll
        for (int k = 0; k < F_ATOM; k++)
            acc = fmaf(xs[r][k], W[k * D_IN + t], acc);
        out[(size_t)(r0 + r) * D_IN + t] = acc;
        Z[(size_t)(r0 + r) * D_IN + t]   = ze * acc;
    }
}

// ---------------- edge scatter: z[dst] += h[src] (one warp per edge) ----------------
__global__ void edge_agg_kernel(float* __restrict__ z, const float* __restrict__ h,
                                const void* __restrict__ ei, int D) {
    int warp = (int)((blockIdx.x * (size_t)blockDim.x + threadIdx.x) >> 5);
    int lane = threadIdx.x & 31;
    if (warp >= N_EDGES) return;
    long long s = load_idx(ei, warp);
    long long d = load_idx(ei, N_EDGES + warp);
    const float* hs = h + (size_t)s * D;
    float*       zd = z + (size_t)d * D;
    for (int c = lane; c < D; c += 32)
        atomicAdd(&zd[c], hs[c]);
}

// ---------------- tf32 tensor-core GEMM, pipelined, LDS.64 fragment layout ----------------
// BM=128 BN=128 BK=16, 256 threads = 8 warps, warp tile 64x32.
// Smem layout: As[buf][kk][lq][m][half] with m-dim padded to 132 ->
//   lq-group byte stride = 132*8 = 1056 == 32 (mod 128): 4 lq groups x 4 lanes x 8B
//   tile the 128B bank window exactly -> conflict-free LDS.64 in both phases.
#define BM 128
#define BN 128
#define BK 16
#define MP 132

__device__ __forceinline__ unsigned int f2tf32(float f) {
    unsigned int u;
    asm("cvt.rna.tf32.f32 %0, %1;" : "=r"(u) : "f"(f));
    return u;
}

__global__ __launch_bounds__(256, 2)
void gemm_tf32(const float* __restrict__ A, const float* __restrict__ B,
               const float* __restrict__ bias, float* __restrict__ C,
               int M, int N, int K, int do_relu,
               float* __restrict__ Z, const float* __restrict__ epsv, int el) {
    __shared__ unsigned int As[2][2][4][MP][2];   // [buf][kk][lq][m][half]
    __shared__ unsigned int Bs[2][2][4][MP][2];   // [buf][kk][lq][n][half]

    int tid  = threadIdx.x;
    int lane = tid & 31;
    int warp = tid >> 5;
    int wr = warp & 1;
    int wc = warp >> 1;
    int block_row = blockIdx.y * BM;
    int block_col = blockIdx.x * BN;

    // A loader: row a_r (0..127), k-slab a_kk (0/1), 8 consecutive k
    int a_r  = tid >> 1;
    int a_kk = tid & 1;
    // B loader: col n_l (0..127), k-slab b_kk (0/1), 8 strided k (coalesced across threads)
    int n_l  = tid & 127;
    int b_kk = tid >> 7;

    float c[4][4][4];
    #pragma unroll
    for (int i = 0; i < 4; i++)
        #pragma unroll
        for (int j = 0; j < 4; j++)
            c[i][j][0] = c[i][j][1] = c[i][j][2] = c[i][j][3] = 0.f;

    int grow = block_row + a_r;
    const int lq = lane & 3;
    const int lg = lane >> 2;
    int mbase = wr * 64;
    int nbase = wc * 32;

    float4 av0, av1;
    float bv[8];

    // ---- prologue: load tile 0 ----
    {
        av0 = make_float4(0.f,0.f,0.f,0.f); av1 = av0;
        if (grow < M) {
            const float* ap = A + (size_t)grow * K + a_kk * 8;
            av0 = *(const float4*)ap;
            av1 = *(const float4*)(ap + 4);
        }
        #pragma unroll
        for (int j = 0; j < 8; j++)
            bv[j] = B[(size_t)(b_kk * 8 + j) * N + block_col + n_l];

        *(uint2*)&As[0][a_kk][0][a_r][0] = make_uint2(f2tf32(av0.x), f2tf32(av1.x));
        *(uint2*)&As[0][a_kk][1][a_r][0] = make_uint2(f2tf32(av0.y), f2tf32(av1.y));
        *(uint2*)&As[0][a_kk][2][a_r][0] = make_uint2(f2tf32(av0.z), f2tf32(av1.z));
        *(uint2*)&As[0][a_kk][3][a_r][0] = make_uint2(f2tf32(av0.w), f2tf32(av1.w));
        #pragma unroll
        for (int j = 0; j < 4; j++)
            *(uint2*)&Bs[0][b_kk][j][n_l][0] = make_uint2(f2tf32(bv[j]), f2tf32(bv[j + 4]));
    }
    __syncthreads();

    int buf = 0;
    for (int k0 = 0; k0 < K; k0 += BK) {
        bool has_next = (k0 + BK) < K;
        // ---- issue global loads for next tile ----
        if (has_next) {
            int kn = k0 + BK;
            av0 = make_float4(0.f,0.f,0.f,0.f); av1 = av0;
            if (grow < M) {
                const float* ap = A + (size_t)grow * K + kn + a_kk * 8;
                av0 = *(const float4*)ap;
                av1 = *(const float4*)(ap + 4);
            }
            #pragma unroll
            for (int j = 0; j < 8; j++)
                bv[j] = B[(size_t)(kn + b_kk * 8 + j) * N + block_col + n_l];
        }

        // ---- compute current tile ----
        #pragma unroll
        for (int kk = 0; kk < 2; kk++) {
            unsigned int af[4][4], bf[4][2];
            #pragma unroll
            for (int mi = 0; mi < 4; mi++) {
                int mb = mbase + mi * 16 + lg;
                uint2 alo = *(const uint2*)&As[buf][kk][lq][mb][0];
                uint2 ahi = *(const uint2*)&As[buf][kk][lq][mb + 8][0];
                af[mi][0] = alo.x; af[mi][2] = alo.y;
                af[mi][1] = ahi.x; af[mi][3] = ahi.y;
            }
            #pragma unroll
            for (int ni = 0; ni < 4; ni++) {
                int nb = nbase + ni * 8 + lg;
                uint2 bu = *(const uint2*)&Bs[buf][kk][lq][nb][0];
                bf[ni][0] = bu.x; bf[ni][1] = bu.y;
            }
            #pragma unroll
            for (int mi = 0; mi < 4; mi++)
                #pragma unroll
                for (int ni = 0; ni < 4; ni++) {
                    asm volatile(
                        "mma.sync.aligned.m16n8k8.row.col.f32.tf32.tf32.f32 "
                        "{%0,%1,%2,%3}, {%4,%5,%6,%7}, {%8,%9}, {%0,%1,%2,%3};"
                        : "+f"(c[mi][ni][0]), "+f"(c[mi][ni][1]),
                          "+f"(c[mi][ni][2]), "+f"(c[mi][ni][3])
                        : "r"(af[mi][0]), "r"(af[mi][1]), "r"(af[mi][2]), "r"(af[mi][3]),
                          "r"(bf[ni][0]), "r"(bf[ni][1]));
                }
        }

        // ---- store next tile into the other buffer ----
        if (has_next) {
            int nb = buf ^ 1;
            *(uint2*)&As[nb][a_kk][0][a_r][0] = make_uint2(f2tf32(av0.x), f2tf32(av1.x));
            *(uint2*)&As[nb][a_kk][1][a_r][0] = make_uint2(f2tf32(av0.y), f2tf32(av1.y));
            *(uint2*)&As[nb][a_kk][2][a_r][0] = make_uint2(f2tf32(av0.z), f2tf32(av1.z));
            *(uint2*)&As[nb][a_kk][3][a_r][0] = make_uint2(f2tf32(av0.w), f2tf32(av1.w));
            #pragma unroll
            for (int j = 0; j < 4; j++)
                *(uint2*)&Bs[nb][b_kk][j][n_l][0] = make_uint2(f2tf32(bv[j]), f2tf32(bv[j + 4]));
        }
        __syncthreads();
        buf ^= 1;
    }

    // epilogue: bias + optional relu (+ optional fused Z = (1+eps)*h)
    float ze = (Z != nullptr) ? (1.0f + epsv[el]) : 0.0f;
    #pragma unroll
    for (int mi = 0; mi < 4; mi++) {
        int r0 = block_row + mbase + mi * 16 + lg;
        int r1 = r0 + 8;
        #pragma unroll
        for (int ni = 0; ni < 4; ni++) {
            int gc = block_col + nbase + ni * 8 + lq * 2;
            float2 bvv = *(const float2*)(bias + gc);
            float2 v0, v1;
            v0.x = c[mi][ni][0] + bvv.x;  v0.y = c[mi][ni][1] + bvv.y;
            v1.x = c[mi][ni][2] + bvv.x;  v1.y = c[mi][ni][3] + bvv.y;
            if (do_relu) {
                v0.x = fmaxf(v0.x, 0.f); v0.y = fmaxf(v0.y, 0.f);
                v1.x = fmaxf(v1.x, 0.f); v1.y = fmaxf(v1.y, 0.f);
            }
            if (r0 < M) {
                *(float2*)(C + (size_t)r0 * N + gc) = v0;
                if (Z) *(float2*)(Z + (size_t)r0 * N + gc) = make_float2(ze * v0.x, ze * v0.y);
            }
            if (r1 < M) {
                *(float2*)(C + (size_t)r1 * N + gc) = v1;
                if (Z) *(float2*)(Z + (size_t)r1 * N + gc) = make_float2(ze * v1.x, ze * v1.y);
            }
        }
    }
}

// ---------------- zero pooled ----------------
__global__ void zero_kernel(float* __restrict__ p, size_t n) {
    size_t i = (size_t)blockIdx.x * blockDim.x + threadIdx.x;
    size_t stride = (size_t)gridDim.x * blockDim.x;
    for (; i < n; i += stride) p[i] = 0.0f;
}

// ---------------- pool: batch SORTED -> run-compress ----------------
__global__ void pool_kernel(const float* __restrict__ h, const void* __restrict__ batch,
                            float* __restrict__ pooled) {
    int n0 = blockIdx.x * 64;
    if (n0 >= N_NODES) return;
    int t = threadIdx.x;
    int nEnd = min(n0 + 64, N_NODES);
    float acc[4] = {0.f, 0.f, 0.f, 0.f};
    long long curg = load_idx(batch, n0);
    for (int n = n0; n < nEnd; n++) {
        long long g = load_idx(batch, n);
        if (g != curg) {
            #pragma unroll
            for (int i = 0; i < 4; i++) {
                atomicAdd(&pooled[(size_t)curg * D_OUT + t + 128 * i], acc[i]);
                acc[i] = 0.f;
            }
            curg = g;
        }
        #pragma unroll
        for (int i = 0; i < 4; i++)
            acc[i] += h[(size_t)n * D_OUT + t + 128 * i];
    }
    #pragma unroll
    for (int i = 0; i < 4; i++)
        atomicAdd(&pooled[(size_t)curg * D_OUT + t + 128 * i], acc[i]);
}

// ---------------- head ----------------
__global__ void task_kernel(const float* __restrict__ pooled, const float* __restrict__ Wt,
                            const float* __restrict__ bt, float* __restrict__ out) {
    int g = blockIdx.x;
    int t = threadIdx.x;
    float s = 0.f;
    #pragma unroll
    for (int i = 0; i < 4; i++)
        s += pooled[(size_t)g * D_OUT + t + 128 * i] * Wt[t + 128 * i];
    #pragma unroll
    for (int o = 16; o > 0; o >>= 1) s += __shfl_down_sync(0xFFFFFFFFu, s, o);
    __shared__ float red[4];
    if ((t & 31) == 0) red[t >> 5] = s;
    __syncthreads();
    if (t == 0) out[g] = red[0] + red[1] + red[2] + red[3] + bt[0];
}

// ---------------- launch ----------------
extern "C" void kernel_launch(void* const* d_in, const int* in_sizes, int n_in,
                              void* d_out, int out_size) {
    const float* x       = (const float*)d_in[0];
    const void*  ei      = d_in[1];
    const void*  batch   = d_in[2];
    const float* W_embed = (const float*)d_in[3];
    const float* b_embed = (const float*)d_in[4];
    const float* eps     = (const float*)d_in[5];
    const float* W1[3]   = {(const float*)d_in[6],  (const float*)d_in[10], (const float*)d_in[14]};
    const float* b1[3]   = {(const float*)d_in[7],  (const float*)d_in[11], (const float*)d_in[15]};
    const float* W2[3]   = {(const float*)d_in[8],  (const float*)d_in[12], (const float*)d_in[16]};
    const float* b2[3]   = {(const float*)d_in[9],  (const float*)d_in[13], (const float*)d_in[17]};
    const float* W_task  = (const float*)d_in[18];
    const float* b_task  = (const float*)d_in[19];
    float* out = (float*)d_out;

    float *bufA, *bufB, *bufZ, *pooled;
    cudaGetSymbolAddress((void**)&bufA, g_bufA);
    cudaGetSymbolAddress((void**)&bufB, g_bufB);
    cudaGetSymbolAddress((void**)&bufZ, g_bufZ);
    cudaGetSymbolAddress((void**)&pooled, g_pooled);

    const int Din[3] = {D_IN,  D_HID, D_HID};
    const int Dh[3]  = {D_HID, D_HID, D_OUT};

    detect_kernel<<<1, 1024>>>((const unsigned int*)ei, in_sizes[1]);

    // embed -> bufA [N,128], and fused bufZ = (1+eps[0])*h
    embed_kernel<<<N_NODES / 4, 128>>>(x, W_embed, b_embed, bufA, bufZ, eps);

    float* hcur = bufA;
    float* hnext = bufB;
    for (int l = 0; l < 3; l++) {
        int dk = Din[l], dh = Dh[l];
        // bufZ already holds (1+eps[l])*hcur (from embed or previous fused epilogue)
        edge_agg_kernel<<<(N_EDGES * 32 + 255) / 256, 256>>>(bufZ, hcur, ei, dk);
        {
            dim3 grid(dh / BN, (N_NODES + BM - 1) / BM);
            gemm_tf32<<<grid, 256>>>(bufZ, W1[l], b1[l], hnext, N_NODES, dh, dk, 1,
                                     nullptr, eps, 0);
        }
        {
            dim3 grid(dh / BN, (N_NODES + BM - 1) / BM);
            // fused: also produce bufZ = (1+eps[l+1]) * h for the next layer (l<2)
            gemm_tf32<<<grid, 256>>>(hnext, W2[l], b2[l], hcur, N_NODES, dh, dh, (l < 2) ? 1 : 0,
                                     (l < 2) ? bufZ : nullptr, eps, l + 1);
        }
    }

    zero_kernel<<<256, 256>>>(pooled, (size_t)N_GRAPHS * D_OUT);
    pool_kernel<<<(N_NODES + 63) / 64, 128>>>(hcur, batch, pooled);

    task_kernel<<<N_GRAPHS, 128>>>(pooled, W_task, b_task, out);
}